// round 1
// baseline (speedup 1.0000x reference)
#include <cuda_runtime.h>
#include <limits.h>
#include <math.h>

#define NCLS 18
#define CF   64
#define NREGO 6
#define VOX  0.04f
// logit(0.15) = ln(0.15/0.85)
#define THR  (-1.7346010553881064f)

__device__ int g_mn[3];
__device__ int g_mx[3];

__global__ void k_init_minmax() {
    int t = threadIdx.x;
    if (t < 3) { g_mn[t] = INT_MAX; g_mx[t] = INT_MIN; }
}

__global__ void k_minmax(const int4* __restrict__ coords, int n) {
    int mnx = INT_MAX, mny = INT_MAX, mnz = INT_MAX;
    int mxx = INT_MIN, mxy = INT_MIN, mxz = INT_MIN;
    for (int i = blockIdx.x * blockDim.x + threadIdx.x; i < n;
         i += gridDim.x * blockDim.x) {
        int4 c = coords[i];
        mnx = min(mnx, c.y); mxx = max(mxx, c.y);
        mny = min(mny, c.z); mxy = max(mxy, c.z);
        mnz = min(mnz, c.w); mxz = max(mxz, c.w);
    }
#pragma unroll
    for (int o = 16; o; o >>= 1) {
        mnx = min(mnx, __shfl_down_sync(0xffffffffu, mnx, o));
        mny = min(mny, __shfl_down_sync(0xffffffffu, mny, o));
        mnz = min(mnz, __shfl_down_sync(0xffffffffu, mnz, o));
        mxx = max(mxx, __shfl_down_sync(0xffffffffu, mxx, o));
        mxy = max(mxy, __shfl_down_sync(0xffffffffu, mxy, o));
        mxz = max(mxz, __shfl_down_sync(0xffffffffu, mxz, o));
    }
    if ((threadIdx.x & 31) == 0) {
        atomicMin(&g_mn[0], mnx); atomicMax(&g_mx[0], mxx);
        atomicMin(&g_mn[1], mny); atomicMax(&g_mx[1], mxy);
        atomicMin(&g_mn[2], mnz); atomicMax(&g_mx[2], mxz);
    }
}

// Rare path: a (point, class) that passed the semantic threshold.
// With this data distribution it is ~never taken; keep it out of the
// hot path's register allocation.
__device__ __noinline__ void rare_class(
    const float* __restrict__ frow,   // feats row in gmem (L2-hot)
    const float* __restrict__ Wc,     // W_ci + c*CF*CF
    const float* __restrict__ gc,     // g_ci + c*CF
    const float* __restrict__ bc,     // b_ci + c*CF
    const float* __restrict__ sWctr,
    const float* __restrict__ sWreg,
    const float* __restrict__ sWcls,
    int c, float bcls, float scale,
    float* __restrict__ o8)           // gmem, 8 floats
{
    float fc[CF];
    for (int e = 0; e < CF; e++) {
        float a = 0.f;
        for (int d = 0; d < CF; d++)
            a = fmaf(frow[d], Wc[d * CF + e], a);
        a = a * gc[e] + bc[e];
        fc[e] = (a > 0.f) ? a : expm1f(a);
    }
    float ctr = 0.f;
    for (int e = 0; e < CF; e++) ctr = fmaf(fc[e], sWctr[e], ctr);
    o8[0] = ctr;
    for (int r = 0; r < NREGO; r++) {
        float a = 0.f;
        for (int e = 0; e < CF; e++) a = fmaf(fc[e], sWreg[e * NREGO + r], a);
        o8[1 + r] = expf(a * scale);
    }
    float cs = 0.f;
    for (int e = 0; e < CF; e++) cs = fmaf(fc[e], sWcls[e * NCLS + c], cs);
    o8[7] = cs + bcls;
}

__global__ void __launch_bounds__(256) k_main(
    const int4*  __restrict__ coords,
    const float* __restrict__ feats,
    const float* __restrict__ W_sem, const float* __restrict__ b_sem,
    const float* __restrict__ W_o1,  const float* __restrict__ g_o1, const float* __restrict__ b_o1,
    const float* __restrict__ W_o2,  const float* __restrict__ g_o2, const float* __restrict__ b_o2,
    const float* __restrict__ W_o3,
    const float* __restrict__ W_ci,  const float* __restrict__ g_ci, const float* __restrict__ b_ci,
    const float* __restrict__ W_ctr, const float* __restrict__ W_reg,
    const float* __restrict__ W_cls, const float* __restrict__ b_cls,
    const float* __restrict__ scales,
    float* __restrict__ out, int n)
{
    __shared__ float sWo1[CF * CF];
    __shared__ float sWo2[CF * CF];
    __shared__ float sWsem[CF * NCLS];
    __shared__ float sWcls[CF * NCLS];
    __shared__ float sWreg[CF * NREGO];
    __shared__ float sWo3[CF * 3];
    __shared__ float sg1[CF], sb1[CF], sg2[CF], sb2[CF], sWctr[CF];
    __shared__ float sbsem[NCLS], sbcls[NCLS], sscale[NCLS];

    const int tid = threadIdx.x;
    for (int i = tid; i < CF * CF; i += blockDim.x) { sWo1[i] = W_o1[i]; sWo2[i] = W_o2[i]; }
    for (int i = tid; i < CF * NCLS; i += blockDim.x) { sWsem[i] = W_sem[i]; sWcls[i] = W_cls[i]; }
    for (int i = tid; i < CF * NREGO; i += blockDim.x) sWreg[i] = W_reg[i];
    for (int i = tid; i < CF * 3; i += blockDim.x) sWo3[i] = W_o3[i];
    for (int i = tid; i < CF; i += blockDim.x) {
        sg1[i] = g_o1[i]; sb1[i] = b_o1[i];
        sg2[i] = g_o2[i]; sb2[i] = b_o2[i];
        sWctr[i] = W_ctr[i];
    }
    for (int i = tid; i < NCLS; i += blockDim.x) {
        sbsem[i] = b_sem[i]; sbcls[i] = b_cls[i]; sscale[i] = scales[i];
    }
    __syncthreads();

    const int nidx = blockIdx.x * blockDim.x + tid;
    if (nidx >= n) return;

    // load feats row into registers
    float f[CF];
    const float4* fr = reinterpret_cast<const float4*>(feats + (size_t)nidx * CF);
#pragma unroll
    for (int i = 0; i < CF / 4; i++) {
        float4 v = fr[i];
        f[4 * i + 0] = v.x; f[4 * i + 1] = v.y;
        f[4 * i + 2] = v.z; f[4 * i + 3] = v.w;
    }

    // semantic scores -> mask bits
    unsigned mask = 0;
#pragma unroll 2
    for (int c = 0; c < NCLS; c++) {
        float a0 = 0.f, a1 = 0.f;
#pragma unroll
        for (int d = 0; d < CF; d += 2) {
            a0 = fmaf(f[d],     sWsem[(d)     * NCLS + c], a0);
            a1 = fmaf(f[d + 1], sWsem[(d + 1) * NCLS + c], a1);
        }
        float s = a0 + a1 + sbsem[c];
        if (s > THR) mask |= (1u << c);
    }

    // offset MLP layer 1
    float h[CF];
#pragma unroll 4
    for (int j = 0; j < CF; j++) {
        float a0 = 0.f, a1 = 0.f;
#pragma unroll
        for (int d = 0; d < CF; d += 2) {
            a0 = fmaf(f[d],     sWo1[(d)     * CF + j], a0);
            a1 = fmaf(f[d + 1], sWo1[(d + 1) * CF + j], a1);
        }
        float a = (a0 + a1) * sg1[j] + sb1[j];
        h[j] = (a > 0.f) ? a : expm1f(a);
    }
    // layer 2
    float h2[CF];
#pragma unroll 4
    for (int j = 0; j < CF; j++) {
        float a0 = 0.f, a1 = 0.f;
#pragma unroll
        for (int d = 0; d < CF; d += 2) {
            a0 = fmaf(h[d],     sWo2[(d)     * CF + j], a0);
            a1 = fmaf(h[d + 1], sWo2[(d + 1) * CF + j], a1);
        }
        float a = (a0 + a1) * sg2[j] + sb2[j];
        h2[j] = (a > 0.f) ? a : expm1f(a);
    }
    // offset head (3)
    float o0 = 0.f, o1 = 0.f, o2 = 0.f;
#pragma unroll
    for (int d = 0; d < CF; d++) {
        o0 = fmaf(h2[d], sWo3[d * 3 + 0], o0);
        o1 = fmaf(h2[d], sWo3[d * 3 + 1], o1);
        o2 = fmaf(h2[d], sWo3[d * 3 + 2], o2);
    }

    // voted = clip(xyz*VOX + offset, min_b, max_b)
    int4 cd = coords[nidx];
    float mnb0 = (float)(g_mn[0] - 1) * VOX, mxb0 = (float)(g_mx[0] + 1) * VOX;
    float mnb1 = (float)(g_mn[1] - 1) * VOX, mxb1 = (float)(g_mx[1] + 1) * VOX;
    float mnb2 = (float)(g_mn[2] - 1) * VOX, mxb2 = (float)(g_mx[2] + 1) * VOX;
    float v0 = fminf(fmaxf((float)cd.y * VOX + o0, mnb0), mxb0);
    float v1 = fminf(fmaxf((float)cd.z * VOX + o1, mnb1), mxb1);
    float v2 = fminf(fmaxf((float)cd.w * VOX + o2, mnb2), mxb2);
    size_t voff = (size_t)NCLS * (size_t)n * 8 + (size_t)nidx * 3;
    out[voff + 0] = v0; out[voff + 1] = v1; out[voff + 2] = v2;

    // per-class heads
    float4* out4 = reinterpret_cast<float4*>(out);
    const size_t row4 = (size_t)nidx * 2;           // 8 floats = 2x float4
    const size_t cstride4 = (size_t)n * 2;
#pragma unroll 1
    for (int c = 0; c < NCLS; c++) {
        if (mask & (1u << c)) {
            rare_class(feats + (size_t)nidx * CF,
                       W_ci + (size_t)c * CF * CF,
                       g_ci + (size_t)c * CF, b_ci + (size_t)c * CF,
                       sWctr, sWreg, sWcls, c, sbcls[c], sscale[c],
                       out + ((size_t)c * (size_t)n + (size_t)nidx) * 8);
        } else {
            float4 p0 = make_float4(0.f, 1.f, 1.f, 1.f);
            float4 p1 = make_float4(1.f, 1.f, 1.f, sbcls[c]);
            out4[(size_t)c * cstride4 + row4 + 0] = p0;
            out4[(size_t)c * cstride4 + row4 + 1] = p1;
        }
    }
}

extern "C" void kernel_launch(void* const* d_in, const int* in_sizes, int n_in,
                              void* d_out, int out_size)
{
    const int*   coords = (const int*)d_in[0];
    const float* feats  = (const float*)d_in[1];
    const float* W_sem  = (const float*)d_in[2];
    const float* b_sem  = (const float*)d_in[3];
    const float* W_o1   = (const float*)d_in[4];
    const float* g_o1   = (const float*)d_in[5];
    const float* b_o1   = (const float*)d_in[6];
    const float* W_o2   = (const float*)d_in[7];
    const float* g_o2   = (const float*)d_in[8];
    const float* b_o2   = (const float*)d_in[9];
    const float* W_o3   = (const float*)d_in[10];
    const float* W_ci   = (const float*)d_in[11];
    const float* g_ci   = (const float*)d_in[12];
    const float* b_ci   = (const float*)d_in[13];
    const float* W_ctr  = (const float*)d_in[14];
    const float* W_reg  = (const float*)d_in[15];
    const float* W_cls  = (const float*)d_in[16];
    const float* b_cls  = (const float*)d_in[17];
    const float* scales = (const float*)d_in[18];
    float* out = (float*)d_out;

    const int n = in_sizes[0] / 4;

    k_init_minmax<<<1, 32>>>();
    k_minmax<<<256, 256>>>((const int4*)coords, n);
    const int blocks = (n + 255) / 256;
    k_main<<<blocks, 256>>>((const int4*)coords, feats,
                            W_sem, b_sem, W_o1, g_o1, b_o1, W_o2, g_o2, b_o2,
                            W_o3, W_ci, g_ci, b_ci, W_ctr, W_reg, W_cls, b_cls,
                            scales, out, n);
}

// round 2
// speedup vs baseline: 1.6067x; 1.6067x over previous
#include <cuda_runtime.h>
#include <limits.h>
#include <math.h>

#define NCLS 18
#define NCLS_PAD 20
#define CF   64
#define NREGO 6
#define VOX  0.04f
// logit(0.15) = ln(0.15/0.85)
#define THR  (-1.7346010553881064f)

__device__ int g_mn[3];
__device__ int g_mx[3];

// ---------- packed f32x2 helpers ----------
#define FMA2(d_, a_, b_, c_) \
    asm("fma.rn.f32x2 %0, %1, %2, %3;" : "=l"(d_) : "l"(a_), "l"(b_), "l"(c_))

__device__ __forceinline__ unsigned long long dup2(float x) {
    unsigned long long r;
    asm("mov.b64 %0, {%1, %1};" : "=l"(r) : "f"(x));
    return r;
}
__device__ __forceinline__ void unpack2(unsigned long long v, float& lo, float& hi) {
    asm("mov.b64 {%0, %1}, %2;" : "=f"(lo), "=f"(hi) : "l"(v));
}

__global__ void k_init_minmax() {
    int t = threadIdx.x;
    if (t < 3) { g_mn[t] = INT_MAX; g_mx[t] = INT_MIN; }
}

__global__ void k_minmax(const int4* __restrict__ coords, int n) {
    int mnx = INT_MAX, mny = INT_MAX, mnz = INT_MAX;
    int mxx = INT_MIN, mxy = INT_MIN, mxz = INT_MIN;
    for (int i = blockIdx.x * blockDim.x + threadIdx.x; i < n;
         i += gridDim.x * blockDim.x) {
        int4 c = coords[i];
        mnx = min(mnx, c.y); mxx = max(mxx, c.y);
        mny = min(mny, c.z); mxy = max(mxy, c.z);
        mnz = min(mnz, c.w); mxz = max(mxz, c.w);
    }
#pragma unroll
    for (int o = 16; o; o >>= 1) {
        mnx = min(mnx, __shfl_down_sync(0xffffffffu, mnx, o));
        mny = min(mny, __shfl_down_sync(0xffffffffu, mny, o));
        mnz = min(mnz, __shfl_down_sync(0xffffffffu, mnz, o));
        mxx = max(mxx, __shfl_down_sync(0xffffffffu, mxx, o));
        mxy = max(mxy, __shfl_down_sync(0xffffffffu, mxy, o));
        mxz = max(mxz, __shfl_down_sync(0xffffffffu, mxz, o));
    }
    if ((threadIdx.x & 31) == 0) {
        atomicMin(&g_mn[0], mnx); atomicMax(&g_mx[0], mxx);
        atomicMin(&g_mn[1], mny); atomicMax(&g_mx[1], mxy);
        atomicMin(&g_mn[2], mnz); atomicMax(&g_mx[2], mxz);
    }
}

// Rare path: a (point, class) that passed the semantic threshold.
// ~Never taken with this data distribution; reads everything from gmem to
// keep the hot path's register allocation clean.
__device__ __noinline__ void rare_class(
    const float* __restrict__ frow,
    const float* __restrict__ Wc,
    const float* __restrict__ gc,
    const float* __restrict__ bc,
    const float* __restrict__ Wctr,
    const float* __restrict__ Wreg,
    const float* __restrict__ Wcls,
    int c, float bcls, float scale,
    float* __restrict__ o8)
{
    float fc[CF];
    for (int e = 0; e < CF; e++) {
        float a = 0.f;
        for (int d = 0; d < CF; d++)
            a = fmaf(frow[d], Wc[d * CF + e], a);
        a = a * gc[e] + bc[e];
        fc[e] = (a > 0.f) ? a : expm1f(a);
    }
    float ctr = 0.f;
    for (int e = 0; e < CF; e++) ctr = fmaf(fc[e], Wctr[e], ctr);
    o8[0] = ctr;
    for (int r = 0; r < NREGO; r++) {
        float a = 0.f;
        for (int e = 0; e < CF; e++) a = fmaf(fc[e], Wreg[e * NREGO + r], a);
        o8[1 + r] = expf(a * scale);
    }
    float cs = 0.f;
    for (int e = 0; e < CF; e++) cs = fmaf(fc[e], Wcls[e * NCLS + c], cs);
    o8[7] = cs + bcls;
}

__global__ void __launch_bounds__(128) k_main(
    const int4*  __restrict__ coords,
    const float* __restrict__ feats,
    const float* __restrict__ W_sem, const float* __restrict__ b_sem,
    const float* __restrict__ W_o1,  const float* __restrict__ g_o1, const float* __restrict__ b_o1,
    const float* __restrict__ W_o2,  const float* __restrict__ g_o2, const float* __restrict__ b_o2,
    const float* __restrict__ W_o3,
    const float* __restrict__ W_ci,  const float* __restrict__ g_ci, const float* __restrict__ b_ci,
    const float* __restrict__ W_ctr, const float* __restrict__ W_reg,
    const float* __restrict__ W_cls, const float* __restrict__ b_cls,
    const float* __restrict__ scales,
    float* __restrict__ out, int n)
{
    __shared__ __align__(16) float sWo1[CF * CF];        // [d][j], j contiguous
    __shared__ __align__(16) float sWo2[CF * CF];
    __shared__ __align__(16) float sWsem[CF * NCLS_PAD]; // [d][c], padded stride 20
    __shared__ __align__(16) float sWo3T[3 * CF];        // [o][d]
    __shared__ float sg1[CF], sb1[CF], sg2[CF], sb2[CF];
    __shared__ float sbsem[NCLS], sbcls[NCLS], sscale[NCLS];

    const int tid = threadIdx.x;
    for (int i = tid; i < CF * CF; i += blockDim.x) { sWo1[i] = W_o1[i]; sWo2[i] = W_o2[i]; }
    for (int i = tid; i < CF * NCLS; i += blockDim.x) {
        int d = i / NCLS, c = i % NCLS;
        sWsem[d * NCLS_PAD + c] = W_sem[i];
    }
    for (int i = tid; i < CF * 3; i += blockDim.x) {
        int d = i / 3, o = i % 3;
        sWo3T[o * CF + d] = W_o3[i];
    }
    for (int i = tid; i < CF; i += blockDim.x) {
        sg1[i] = g_o1[i]; sb1[i] = b_o1[i];
        sg2[i] = g_o2[i]; sb2[i] = b_o2[i];
    }
    for (int i = tid; i < NCLS; i += blockDim.x) {
        sbsem[i] = b_sem[i]; sbcls[i] = b_cls[i]; sscale[i] = scales[i];
    }
    __syncthreads();

    const int nidx = blockIdx.x * blockDim.x + tid;
    if (nidx >= n) return;

    // feats row -> registers
    float f[CF];
    {
        const float4* fr = reinterpret_cast<const float4*>(feats + (size_t)nidx * CF);
#pragma unroll
        for (int i = 0; i < CF / 4; i++) {
            float4 v = fr[i];
            f[4 * i + 0] = v.x; f[4 * i + 1] = v.y;
            f[4 * i + 2] = v.z; f[4 * i + 3] = v.w;
        }
    }

    // ---------------- semantic scores (f32x2 over class pairs) ----------------
    unsigned long long sacc[9];
#pragma unroll
    for (int p = 0; p < 9; p++) sacc[p] = 0ULL;
#pragma unroll
    for (int d = 0; d < CF; d++) {
        unsigned long long fd = dup2(f[d]);
        const ulonglong2* wp = reinterpret_cast<const ulonglong2*>(&sWsem[d * NCLS_PAD]);
        ulonglong2 w01 = wp[0];
        ulonglong2 w23 = wp[1];
        ulonglong2 w45 = wp[2];
        ulonglong2 w67 = wp[3];
        unsigned long long w8 =
            *reinterpret_cast<const unsigned long long*>(&sWsem[d * NCLS_PAD + 16]);
        FMA2(sacc[0], fd, w01.x, sacc[0]);
        FMA2(sacc[1], fd, w01.y, sacc[1]);
        FMA2(sacc[2], fd, w23.x, sacc[2]);
        FMA2(sacc[3], fd, w23.y, sacc[3]);
        FMA2(sacc[4], fd, w45.x, sacc[4]);
        FMA2(sacc[5], fd, w45.y, sacc[5]);
        FMA2(sacc[6], fd, w67.x, sacc[6]);
        FMA2(sacc[7], fd, w67.y, sacc[7]);
        FMA2(sacc[8], fd, w8,    sacc[8]);
    }
    unsigned mask = 0;
#pragma unroll
    for (int p = 0; p < 9; p++) {
        float lo, hi;
        unpack2(sacc[p], lo, hi);
        if (lo + sbsem[2 * p]     > THR) mask |= (1u << (2 * p));
        if (hi + sbsem[2 * p + 1] > THR) mask |= (1u << (2 * p + 1));
    }

    // ---------------- offset MLP layer 1 (f32x2 over output pairs) ----------------
    unsigned long long acc[32];
#pragma unroll
    for (int p = 0; p < 32; p++) acc[p] = 0ULL;
#pragma unroll
    for (int d = 0; d < CF; d++) {
        unsigned long long fd = dup2(f[d]);
        const ulonglong2* wp = reinterpret_cast<const ulonglong2*>(&sWo1[d * CF]);
#pragma unroll
        for (int q = 0; q < 16; q++) {
            ulonglong2 w = wp[q];
            FMA2(acc[2 * q],     fd, w.x, acc[2 * q]);
            FMA2(acc[2 * q + 1], fd, w.y, acc[2 * q + 1]);
        }
    }
    // activation: h overwrites f
#pragma unroll
    for (int p = 0; p < 32; p++) {
        float lo, hi;
        unpack2(acc[p], lo, hi);
        float a0 = lo * sg1[2 * p]     + sb1[2 * p];
        float a1 = hi * sg1[2 * p + 1] + sb1[2 * p + 1];
        float e0 = __expf(a0) - 1.f;
        float e1 = __expf(a1) - 1.f;
        f[2 * p]     = (a0 > 0.f) ? a0 : e0;
        f[2 * p + 1] = (a1 > 0.f) ? a1 : e1;
    }

    // ---------------- offset MLP layer 2 ----------------
#pragma unroll
    for (int p = 0; p < 32; p++) acc[p] = 0ULL;
#pragma unroll
    for (int d = 0; d < CF; d++) {
        unsigned long long fd = dup2(f[d]);
        const ulonglong2* wp = reinterpret_cast<const ulonglong2*>(&sWo2[d * CF]);
#pragma unroll
        for (int q = 0; q < 16; q++) {
            ulonglong2 w = wp[q];
            FMA2(acc[2 * q],     fd, w.x, acc[2 * q]);
            FMA2(acc[2 * q + 1], fd, w.y, acc[2 * q + 1]);
        }
    }
#pragma unroll
    for (int p = 0; p < 32; p++) {
        float lo, hi;
        unpack2(acc[p], lo, hi);
        float a0 = lo * sg2[2 * p]     + sb2[2 * p];
        float a1 = hi * sg2[2 * p + 1] + sb2[2 * p + 1];
        float e0 = __expf(a0) - 1.f;
        float e1 = __expf(a1) - 1.f;
        f[2 * p]     = (a0 > 0.f) ? a0 : e0;
        f[2 * p + 1] = (a1 > 0.f) ? a1 : e1;
    }

    // ---------------- offset head (3 outputs, scalar dot over transposed W) ----
    float o3v[3];
#pragma unroll
    for (int o = 0; o < 3; o++) {
        float a0 = 0.f, a1 = 0.f;
        const float4* wr = reinterpret_cast<const float4*>(&sWo3T[o * CF]);
#pragma unroll
        for (int q = 0; q < 16; q++) {
            float4 w = wr[q];
            a0 = fmaf(f[4 * q + 0], w.x, a0);
            a1 = fmaf(f[4 * q + 1], w.y, a1);
            a0 = fmaf(f[4 * q + 2], w.z, a0);
            a1 = fmaf(f[4 * q + 3], w.w, a1);
        }
        o3v[o] = a0 + a1;
    }

    // voted = clip(xyz*VOX + offset, min_b, max_b)
    int4 cd = coords[nidx];
    float mnb0 = (float)(g_mn[0] - 1) * VOX, mxb0 = (float)(g_mx[0] + 1) * VOX;
    float mnb1 = (float)(g_mn[1] - 1) * VOX, mxb1 = (float)(g_mx[1] + 1) * VOX;
    float mnb2 = (float)(g_mn[2] - 1) * VOX, mxb2 = (float)(g_mx[2] + 1) * VOX;
    float v0 = fminf(fmaxf((float)cd.y * VOX + o3v[0], mnb0), mxb0);
    float v1 = fminf(fmaxf((float)cd.z * VOX + o3v[1], mnb1), mxb1);
    float v2 = fminf(fmaxf((float)cd.w * VOX + o3v[2], mnb2), mxb2);
    size_t voff = (size_t)NCLS * (size_t)n * 8 + (size_t)nidx * 3;
    out[voff + 0] = v0; out[voff + 1] = v1; out[voff + 2] = v2;

    // ---------------- per-class outputs ----------------
    float4* out4 = reinterpret_cast<float4*>(out);
    const size_t row4 = (size_t)nidx * 2;
    const size_t cstride4 = (size_t)n * 2;
    if (mask == 0) {
        // common case: all classes masked out -> constant rows
#pragma unroll 1
        for (int c = 0; c < NCLS; c++) {
            float4 p0 = make_float4(0.f, 1.f, 1.f, 1.f);
            float4 p1 = make_float4(1.f, 1.f, 1.f, sbcls[c]);
            out4[(size_t)c * cstride4 + row4 + 0] = p0;
            out4[(size_t)c * cstride4 + row4 + 1] = p1;
        }
    } else {
#pragma unroll 1
        for (int c = 0; c < NCLS; c++) {
            if (mask & (1u << c)) {
                rare_class(feats + (size_t)nidx * CF,
                           W_ci + (size_t)c * CF * CF,
                           g_ci + (size_t)c * CF, b_ci + (size_t)c * CF,
                           W_ctr, W_reg, W_cls, c, sbcls[c], sscale[c],
                           out + ((size_t)c * (size_t)n + (size_t)nidx) * 8);
            } else {
                float4 p0 = make_float4(0.f, 1.f, 1.f, 1.f);
                float4 p1 = make_float4(1.f, 1.f, 1.f, sbcls[c]);
                out4[(size_t)c * cstride4 + row4 + 0] = p0;
                out4[(size_t)c * cstride4 + row4 + 1] = p1;
            }
        }
    }
}

extern "C" void kernel_launch(void* const* d_in, const int* in_sizes, int n_in,
                              void* d_out, int out_size)
{
    const int*   coords = (const int*)d_in[0];
    const float* feats  = (const float*)d_in[1];
    const float* W_sem  = (const float*)d_in[2];
    const float* b_sem  = (const float*)d_in[3];
    const float* W_o1   = (const float*)d_in[4];
    const float* g_o1   = (const float*)d_in[5];
    const float* b_o1   = (const float*)d_in[6];
    const float* W_o2   = (const float*)d_in[7];
    const float* g_o2   = (const float*)d_in[8];
    const float* b_o2   = (const float*)d_in[9];
    const float* W_o3   = (const float*)d_in[10];
    const float* W_ci   = (const float*)d_in[11];
    const float* g_ci   = (const float*)d_in[12];
    const float* b_ci   = (const float*)d_in[13];
    const float* W_ctr  = (const float*)d_in[14];
    const float* W_reg  = (const float*)d_in[15];
    const float* W_cls  = (const float*)d_in[16];
    const float* b_cls  = (const float*)d_in[17];
    const float* scales = (const float*)d_in[18];
    float* out = (float*)d_out;

    const int n = in_sizes[0] / 4;

    k_init_minmax<<<1, 32>>>();
    k_minmax<<<256, 256>>>((const int4*)coords, n);
    const int blocks = (n + 127) / 128;
    k_main<<<blocks, 128>>>((const int4*)coords, feats,
                            W_sem, b_sem, W_o1, g_o1, b_o1, W_o2, g_o2, b_o2,
                            W_o3, W_ci, g_ci, b_ci, W_ctr, W_reg, W_cls, b_cls,
                            scales, out, n);
}

// round 7
// speedup vs baseline: 3.8200x; 2.3776x over previous
#include <cuda_runtime.h>
#include <cuda_bf16.h>
#include <stdint.h>
#include <limits.h>
#include <math.h>

#define NCLS 18
#define CF   64
#define NREGO 6
#define VOX  0.04f
// logit(0.15)
#define THR  (-1.7346010553881064f)

#define BLK_PTS 128
#define NWARP 8
#define WARP_PTS 16
#define NTHD 256

// smem layout (bytes). Swizzled bf16 tiles have 128B rows.
#define OFF_X    0        // 128 x 64 bf16 (points)
#define OFF_W1   16384    // 64 x 64 bf16
#define OFF_W2   24576    // 64 x 64 bf16
#define OFF_WSEM 32768    // 64 x (24 used of 64) bf16
#define OFF_W3T  40960    // 3 x 64 f32
#define OFF_G1   (OFF_W3T + 768)
#define OFF_B1   (OFF_G1 + 256)
#define OFF_G2   (OFF_B1 + 256)
#define OFF_B2   (OFF_G2 + 256)
#define OFF_THR  (OFF_B2 + 256)    // 24 f32
#define OFF_BCLS (OFF_THR + 96)    // 18 f32
#define OFF_MASK (OFF_BCLS + 96)   // 8*16 u32
#define SMEM_TOTAL (OFF_MASK + 512)

__device__ int g_mn[3];
__device__ int g_mx[3];

__global__ void k_init_minmax() {
    int t = threadIdx.x;
    if (t < 3) { g_mn[t] = INT_MAX; g_mx[t] = INT_MIN; }
}

__global__ void k_minmax(const int4* __restrict__ coords, int n) {
    int mnx = INT_MAX, mny = INT_MAX, mnz = INT_MAX;
    int mxx = INT_MIN, mxy = INT_MIN, mxz = INT_MIN;
    for (int i = blockIdx.x * blockDim.x + threadIdx.x; i < n;
         i += gridDim.x * blockDim.x) {
        int4 c = coords[i];
        mnx = min(mnx, c.y); mxx = max(mxx, c.y);
        mny = min(mny, c.z); mxy = max(mxy, c.z);
        mnz = min(mnz, c.w); mxz = max(mxz, c.w);
    }
#pragma unroll
    for (int o = 16; o; o >>= 1) {
        mnx = min(mnx, __shfl_down_sync(0xffffffffu, mnx, o));
        mny = min(mny, __shfl_down_sync(0xffffffffu, mny, o));
        mnz = min(mnz, __shfl_down_sync(0xffffffffu, mnz, o));
        mxx = max(mxx, __shfl_down_sync(0xffffffffu, mxx, o));
        mxy = max(mxy, __shfl_down_sync(0xffffffffu, mxy, o));
        mxz = max(mxz, __shfl_down_sync(0xffffffffu, mxz, o));
    }
    if ((threadIdx.x & 31) == 0) {
        atomicMin(&g_mn[0], mnx); atomicMax(&g_mx[0], mxx);
        atomicMin(&g_mn[1], mny); atomicMax(&g_mx[1], mxy);
        atomicMin(&g_mn[2], mnz); atomicMax(&g_mx[2], mxz);
    }
}

// ---------------- rare path (approximately never taken) ----------------
__device__ __noinline__ void rare_class(
    const float* __restrict__ frow, const float* __restrict__ Wc,
    const float* __restrict__ gc, const float* __restrict__ bc,
    const float* __restrict__ Wctr, const float* __restrict__ Wreg,
    const float* __restrict__ Wcls, int c, float bcls, float scale,
    float* __restrict__ o8)
{
    float fc[CF];
    for (int e = 0; e < CF; e++) {
        float a = 0.f;
        for (int d = 0; d < CF; d++) a = fmaf(frow[d], Wc[d * CF + e], a);
        a = a * gc[e] + bc[e];
        fc[e] = (a > 0.f) ? a : expm1f(a);
    }
    float ctr = 0.f;
    for (int e = 0; e < CF; e++) ctr = fmaf(fc[e], Wctr[e], ctr);
    o8[0] = ctr;
    for (int r = 0; r < NREGO; r++) {
        float a = 0.f;
        for (int e = 0; e < CF; e++) a = fmaf(fc[e], Wreg[e * NREGO + r], a);
        o8[1 + r] = expf(a * scale);
    }
    float cs = 0.f;
    for (int e = 0; e < CF; e++) cs = fmaf(fc[e], Wcls[e * NCLS + c], cs);
    o8[7] = cs + bcls;
}

// ---------------- helpers ----------------
__device__ __forceinline__ unsigned pack_bf16x2(float hi, float lo) {
    unsigned r;
    asm("cvt.rn.bf16x2.f32 %0, %1, %2;" : "=r"(r) : "f"(hi), "f"(lo));
    return r;
}

__device__ __forceinline__ void mma16816(
    float& c0, float& c1, float& c2, float& c3,
    unsigned a0, unsigned a1, unsigned a2, unsigned a3,
    unsigned b0, unsigned b1)
{
    asm volatile(
        "mma.sync.aligned.m16n8k16.row.col.f32.bf16.bf16.f32 "
        "{%0,%1,%2,%3}, {%4,%5,%6,%7}, {%8,%9}, {%0,%1,%2,%3};"
        : "+f"(c0), "+f"(c1), "+f"(c2), "+f"(c3)
        : "r"(a0), "r"(a1), "r"(a2), "r"(a3), "r"(b0), "r"(b1));
}

// Load a k16 x n8 B tile (n-tile j, k-tile t) from a swizzled 128B-row
// row-major [k][n] bf16 tile in smem.
__device__ __forceinline__ void ldB(uint32_t tile_sb, int j, int t, int lane,
                                    unsigned& b0, unsigned& b1)
{
    int k = t * 16 + (lane & 15);
    uint32_t off = (uint32_t)k * 128u + (uint32_t)((j ^ (k & 7)) * 16);
    asm volatile("ldmatrix.sync.aligned.m8n8.x2.trans.shared.b16 {%0,%1}, [%2];"
                 : "=r"(b0), "=r"(b1) : "r"(tile_sb + off));
}

__global__ void __launch_bounds__(NTHD) k_main(
    const int4*  __restrict__ coords,
    const float* __restrict__ feats,
    const float* __restrict__ W_sem, const float* __restrict__ b_sem,
    const float* __restrict__ W_o1,  const float* __restrict__ g_o1, const float* __restrict__ b_o1,
    const float* __restrict__ W_o2,  const float* __restrict__ g_o2, const float* __restrict__ b_o2,
    const float* __restrict__ W_o3,
    const float* __restrict__ W_ci,  const float* __restrict__ g_ci, const float* __restrict__ b_ci,
    const float* __restrict__ W_ctr, const float* __restrict__ W_reg,
    const float* __restrict__ W_cls, const float* __restrict__ b_cls,
    const float* __restrict__ scales,
    float* __restrict__ out, int n)
{
    __shared__ __align__(1024) char sm[SMEM_TOTAL];
    const int tid = threadIdx.x;
    const int base = blockIdx.x * BLK_PTS;

    // ---------------- stage X (bf16, swizzled) ----------------
    {
        const float4* f4 = reinterpret_cast<const float4*>(feats);
        for (int i = tid; i < BLK_PTS * 16; i += NTHD) {
            int row = i >> 4, c4 = i & 15;
            int p = base + row;
            float4 v = make_float4(0.f, 0.f, 0.f, 0.f);
            if (p < n) v = f4[(size_t)p * 16 + c4];
            unsigned lo = pack_bf16x2(v.y, v.x);
            unsigned hi = pack_bf16x2(v.w, v.z);
            unsigned long long pk = (unsigned long long)lo |
                                    ((unsigned long long)hi << 32);
            uint32_t off = (uint32_t)row * 128u + (uint32_t)c4 * 8u;
            off ^= ((off >> 3) & 0x70u);
            *reinterpret_cast<unsigned long long*>(sm + OFF_X + off) = pk;
        }
    }
    // ---------------- stage W1 / W2 ----------------
    {
        const float4* w14 = reinterpret_cast<const float4*>(W_o1);
        const float4* w24 = reinterpret_cast<const float4*>(W_o2);
        for (int i = tid; i < 64 * 16; i += NTHD) {
            int row = i >> 4, c4 = i & 15;
            uint32_t off = (uint32_t)row * 128u + (uint32_t)c4 * 8u;
            off ^= ((off >> 3) & 0x70u);
            float4 v = w14[i];
            unsigned lo = pack_bf16x2(v.y, v.x);
            unsigned hi = pack_bf16x2(v.w, v.z);
            *reinterpret_cast<unsigned long long*>(sm + OFF_W1 + off) =
                (unsigned long long)lo | ((unsigned long long)hi << 32);
            float4 u = w24[i];
            lo = pack_bf16x2(u.y, u.x);
            hi = pack_bf16x2(u.w, u.z);
            *reinterpret_cast<unsigned long long*>(sm + OFF_W2 + off) =
                (unsigned long long)lo | ((unsigned long long)hi << 32);
        }
    }
    // ---------------- stage W_sem (cols 0..17, zero-pad to 24) ----------------
    for (int i = tid; i < 64 * 24; i += NTHD) {
        int row = i / 24, col = i % 24;
        float v = (col < NCLS) ? W_sem[row * NCLS + col] : 0.f;
        uint32_t off = (uint32_t)row * 128u + (uint32_t)col * 2u;
        off ^= ((off >> 3) & 0x70u);
        *reinterpret_cast<__nv_bfloat16*>(sm + OFF_WSEM + off) = __float2bfloat16(v);
    }
    // ---------------- small f32 tables ----------------
    {
        float* sw3t = (float*)(sm + OFF_W3T);
        for (int i = tid; i < 192; i += NTHD) sw3t[(i % 3) * 64 + (i / 3)] = W_o3[i];
        float* sg1 = (float*)(sm + OFF_G1);
        float* sb1 = (float*)(sm + OFF_B1);
        float* sg2 = (float*)(sm + OFF_G2);
        float* sb2 = (float*)(sm + OFF_B2);
        for (int i = tid; i < 64; i += NTHD) {
            sg1[i] = g_o1[i]; sb1[i] = b_o1[i];
            sg2[i] = g_o2[i]; sb2[i] = b_o2[i];
        }
        float* sthr = (float*)(sm + OFF_THR);
        for (int i = tid; i < 24; i += NTHD)
            sthr[i] = (i < NCLS) ? (THR - b_sem[i]) : 3.0e38f;
        float* sbc = (float*)(sm + OFF_BCLS);
        for (int i = tid; i < NCLS; i += NTHD) sbc[i] = b_cls[i];
    }
    __syncthreads();

    const int warp = tid >> 5;
    const int lane = tid & 31;
    const int g = lane >> 2;   // row group within m16 tile
    const int c = lane & 3;    // col pair id
    const int wbase = warp * WARP_PTS;
    const uint32_t sb = (uint32_t)__cvta_generic_to_shared(sm);

    // ---------------- ldmatrix A (X), 4 k-tiles ----------------
    unsigned ax[4][4];
    {
        int m = lane >> 3, r = lane & 7;
        int arow = wbase + ((m & 1) << 3) + r;
        int kc = m >> 1;
#pragma unroll
        for (int t = 0; t < 4; t++) {
            uint32_t off = (uint32_t)arow * 128u +
                           (uint32_t)(((2 * t + kc) ^ (arow & 7)) * 16);
            uint32_t a = sb + OFF_X + off;
            asm volatile("ldmatrix.sync.aligned.m8n8.x4.shared.b16 {%0,%1,%2,%3}, [%4];"
                         : "=r"(ax[t][0]), "=r"(ax[t][1]),
                           "=r"(ax[t][2]), "=r"(ax[t][3]) : "r"(a));
        }
    }

    // ---------------- semantic scores -> masks ----------------
    unsigned mlo = 0, mhi = 0;
    {
        const float* sthr = (const float*)(sm + OFF_THR);
#pragma unroll
        for (int j = 0; j < 3; j++) {
            float c0 = 0.f, c1 = 0.f, c2 = 0.f, c3 = 0.f;
#pragma unroll
            for (int t = 0; t < 4; t++) {
                unsigned b0, b1;
                ldB(sb + OFF_WSEM, j, t, lane, b0, b1);
                mma16816(c0, c1, c2, c3, ax[t][0], ax[t][1], ax[t][2], ax[t][3], b0, b1);
            }
            int col = 8 * j + 2 * c;
            float t0 = sthr[col], t1 = sthr[col + 1];
            if (c0 > t0) mlo |= 1u << col;
            if (c1 > t1) mlo |= 1u << (col + 1);
            if (c2 > t0) mhi |= 1u << col;
            if (c3 > t1) mhi |= 1u << (col + 1);
        }
        mlo |= __shfl_xor_sync(~0u, mlo, 1); mlo |= __shfl_xor_sync(~0u, mlo, 2);
        mhi |= __shfl_xor_sync(~0u, mhi, 1); mhi |= __shfl_xor_sync(~0u, mhi, 2);
    }

    // ---------------- layer 1: h1 = elu(X@W1 * g1 + b1) -> A frags ----------------
    unsigned a1r[4][4];
    {
#pragma unroll
        for (int j = 0; j < 8; j++) {
            float c0 = 0.f, c1 = 0.f, c2 = 0.f, c3 = 0.f;
#pragma unroll
            for (int t = 0; t < 4; t++) {
                unsigned b0, b1;
                ldB(sb + OFF_W1, j, t, lane, b0, b1);
                mma16816(c0, c1, c2, c3, ax[t][0], ax[t][1], ax[t][2], ax[t][3], b0, b1);
            }
            int col = 8 * j + 2 * c;
            float2 gg = *(const float2*)((const float*)(sm + OFF_G1) + col);
            float2 bb = *(const float2*)((const float*)(sm + OFF_B1) + col);
            float a0 = c0 * gg.x + bb.x; a0 = (a0 > 0.f) ? a0 : (__expf(a0) - 1.f);
            float a1 = c1 * gg.y + bb.y; a1 = (a1 > 0.f) ? a1 : (__expf(a1) - 1.f);
            float a2 = c2 * gg.x + bb.x; a2 = (a2 > 0.f) ? a2 : (__expf(a2) - 1.f);
            float a3 = c3 * gg.y + bb.y; a3 = (a3 > 0.f) ? a3 : (__expf(a3) - 1.f);
            a1r[j >> 1][((j & 1) << 1) + 0] = pack_bf16x2(a1, a0);
            a1r[j >> 1][((j & 1) << 1) + 1] = pack_bf16x2(a3, a2);
        }
    }

    // ---------------- layer 2: h2 = elu(h1@W2 * g2 + b2), keep f32 ----------------
    float h2f[32];
    {
#pragma unroll
        for (int j = 0; j < 8; j++) {
            float c0 = 0.f, c1 = 0.f, c2 = 0.f, c3 = 0.f;
#pragma unroll
            for (int t = 0; t < 4; t++) {
                unsigned b0, b1;
                ldB(sb + OFF_W2, j, t, lane, b0, b1);
                mma16816(c0, c1, c2, c3, a1r[t][0], a1r[t][1], a1r[t][2], a1r[t][3], b0, b1);
            }
            int col = 8 * j + 2 * c;
            float2 gg = *(const float2*)((const float*)(sm + OFF_G2) + col);
            float2 bb = *(const float2*)((const float*)(sm + OFF_B2) + col);
            float a0 = c0 * gg.x + bb.x; a0 = (a0 > 0.f) ? a0 : (__expf(a0) - 1.f);
            float a1 = c1 * gg.y + bb.y; a1 = (a1 > 0.f) ? a1 : (__expf(a1) - 1.f);
            float a2 = c2 * gg.x + bb.x; a2 = (a2 > 0.f) ? a2 : (__expf(a2) - 1.f);
            float a3 = c3 * gg.y + bb.y; a3 = (a3 > 0.f) ? a3 : (__expf(a3) - 1.f);
            h2f[4 * j + 0] = a0; h2f[4 * j + 1] = a1;
            h2f[4 * j + 2] = a2; h2f[4 * j + 3] = a3;
        }
    }

    // ---------------- offset head: 3 dots per row, quad-reduced ----------------
    float vlo[3], vhi[3];
    {
        const float* sw3t = (const float*)(sm + OFF_W3T);
#pragma unroll
        for (int o = 0; o < 3; o++) {
            float alo = 0.f, ahi = 0.f;
#pragma unroll
            for (int j = 0; j < 8; j++) {
                float2 w = *(const float2*)&sw3t[o * 64 + 8 * j + 2 * c];
                alo = fmaf(h2f[4 * j + 0], w.x, alo);
                alo = fmaf(h2f[4 * j + 1], w.y, alo);
                ahi = fmaf(h2f[4 * j + 2], w.x, ahi);
                ahi = fmaf(h2f[4 * j + 3], w.y, ahi);
            }
            alo += __shfl_xor_sync(~0u, alo, 1);
            alo += __shfl_xor_sync(~0u, alo, 2);
            ahi += __shfl_xor_sync(~0u, ahi, 1);
            ahi += __shfl_xor_sync(~0u, ahi, 2);
            vlo[o] = alo; vhi[o] = ahi;
        }
    }

    // ---------------- voted, masks, rare path (writer lanes) ----------------
    unsigned* smask = (unsigned*)(sm + OFF_MASK);
    if (c == 0) {
        smask[warp * 16 + g] = mlo;
        smask[warp * 16 + 8 + g] = mhi;

        float mnb0 = (float)(g_mn[0] - 1) * VOX, mxb0 = (float)(g_mx[0] + 1) * VOX;
        float mnb1 = (float)(g_mn[1] - 1) * VOX, mxb1 = (float)(g_mx[1] + 1) * VOX;
        float mnb2 = (float)(g_mn[2] - 1) * VOX, mxb2 = (float)(g_mx[2] + 1) * VOX;
        size_t vbase = (size_t)NCLS * (size_t)n * 8;

        int plo = base + wbase + g;
        int phi = plo + 8;
        if (plo < n) {
            int4 cd = coords[plo];
            out[vbase + (size_t)plo * 3 + 0] = fminf(fmaxf((float)cd.y * VOX + vlo[0], mnb0), mxb0);
            out[vbase + (size_t)plo * 3 + 1] = fminf(fmaxf((float)cd.z * VOX + vlo[1], mnb1), mxb1);
            out[vbase + (size_t)plo * 3 + 2] = fminf(fmaxf((float)cd.w * VOX + vlo[2], mnb2), mxb2);
            unsigned m = mlo;
            while (m) {
                int cc = __ffs(m) - 1; m &= m - 1;
                rare_class(feats + (size_t)plo * CF, W_ci + (size_t)cc * CF * CF,
                           g_ci + cc * CF, b_ci + cc * CF, W_ctr, W_reg, W_cls,
                           cc, b_cls[cc], scales[cc],
                           out + ((size_t)cc * n + plo) * 8);
            }
        }
        if (phi < n) {
            int4 cd = coords[phi];
            out[vbase + (size_t)phi * 3 + 0] = fminf(fmaxf((float)cd.y * VOX + vhi[0], mnb0), mxb0);
            out[vbase + (size_t)phi * 3 + 1] = fminf(fmaxf((float)cd.z * VOX + vhi[1], mnb1), mxb1);
            out[vbase + (size_t)phi * 3 + 2] = fminf(fmaxf((float)cd.w * VOX + vhi[2], mnb2), mxb2);
            unsigned m = mhi;
            while (m) {
                int cc = __ffs(m) - 1; m &= m - 1;
                rare_class(feats + (size_t)phi * CF, W_ci + (size_t)cc * CF * CF,
                           g_ci + cc * CF, b_ci + cc * CF, W_ctr, W_reg, W_cls,
                           cc, b_cls[cc], scales[cc],
                           out + ((size_t)cc * n + phi) * 8);
            }
        }
    }
    __syncwarp();

    // ---------------- constant epilogue: [18][N][8] ----------------
    {
        int row = lane >> 1, half = lane & 1;
        int p = base + wbase + row;
        if (p < n) {
            unsigned rm = smask[warp * 16 + row];
            const float* sbc = (const float*)(sm + OFF_BCLS);
            float4* o4 = reinterpret_cast<float4*>(out);
            size_t idxb = (size_t)p * 2 + half;
            size_t cst = (size_t)n * 2;
            float4 v0 = make_float4(0.f, 1.f, 1.f, 1.f);
#pragma unroll 1
            for (int cc = 0; cc < NCLS; cc++) {
                if (!((rm >> cc) & 1u)) {
                    float4 v = half ? make_float4(1.f, 1.f, 1.f, sbc[cc]) : v0;
                    o4[(size_t)cc * cst + idxb] = v;
                }
            }
        }
    }
}

extern "C" void kernel_launch(void* const* d_in, const int* in_sizes, int n_in,
                              void* d_out, int out_size)
{
    const int*   coords = (const int*)d_in[0];
    const float* feats  = (const float*)d_in[1];
    const float* W_sem  = (const float*)d_in[2];
    const float* b_sem  = (const float*)d_in[3];
    const float* W_o1   = (const float*)d_in[4];
    const float* g_o1   = (const float*)d_in[5];
    const float* b_o1   = (const float*)d_in[6];
    const float* W_o2   = (const float*)d_in[7];
    const float* g_o2   = (const float*)d_in[8];
    const float* b_o2   = (const float*)d_in[9];
    const float* W_o3   = (const float*)d_in[10];
    const float* W_ci   = (const float*)d_in[11];
    const float* g_ci   = (const float*)d_in[12];
    const float* b_ci   = (const float*)d_in[13];
    const float* W_ctr  = (const float*)d_in[14];
    const float* W_reg  = (const float*)d_in[15];
    const float* W_cls  = (const float*)d_in[16];
    const float* b_cls  = (const float*)d_in[17];
    const float* scales = (const float*)d_in[18];
    float* out = (float*)d_out;

    const int n = in_sizes[0] / 4;

    k_init_minmax<<<1, 32>>>();
    k_minmax<<<256, 256>>>((const int4*)coords, n);
    const int blocks = (n + BLK_PTS - 1) / BLK_PTS;
    k_main<<<blocks, NTHD>>>((const int4*)coords, feats,
                             W_sem, b_sem, W_o1, g_o1, b_o1, W_o2, g_o2, b_o2,
                             W_o3, W_ci, g_ci, b_ci, W_ctr, W_reg, W_cls, b_cls,
                             scales, out, n);
}